// round 14
// baseline (speedup 1.0000x reference)
#include <cuda_runtime.h>
#include <cuda_fp16.h>
#include <cstdint>

#define OFF_Q    0ull
#define OFF_LOSS 2097152ull
#define OFF_PERP 2097153ull
#define OFF_ENC  2097154ull
#define OFF_DIST 35651586ull

#define BSTRIDE 136   // u32 stride: conflict-free b-frag LDS
#define DSTRIDE 72    // u32 stride: conflict-free s_d STS/LDS (72 mod 32 == 8)

// dynamic smem partition (bytes)
#define SMO_B  0          // uint32[2*32*136] = 34816 (B hi | B lo)
#define SMO_D  34816      // float[128*72]    = 36864 (dist staging, 64-col half)
#define SMO_WN 71680      // float[512] this half's code norms
#define SMEM_BYTES 73728  // x3 blocks = 221184 <= 228KB

__device__ int                g_counts[1024];
__device__ float              g_loss_sum;
__device__ float              g_wnorm[1024];
__device__ unsigned           g_ticket;
__device__ unsigned long long g_best[32768];
// codebook packed fp16 hi/lo, layout [chunk(8)][kp(32)][code(128)] u32
__device__ __align__(16) uint32_t g_whi[32768];
__device__ __align__(16) uint32_t g_wlo[32768];

static __device__ __forceinline__ void split2(float x, float y,
                                              uint32_t& hi, uint32_t& lo) {
    __half hx = __float2half_rn(x), hy = __float2half_rn(y);
    float rx = x - __half2float(hx), ry = y - __half2float(hy);
    __half2 h = __halves2half2(hx, hy);
    __half2 l = __floats2half2_rn(rx, ry);
    hi = *(uint32_t*)&h;
    lo = *(uint32_t*)&l;
}

static __device__ __forceinline__ void mma16816(float* c, const uint32_t* a,
                                                uint32_t b0, uint32_t b1) {
    asm volatile(
        "mma.sync.aligned.m16n8k16.row.col.f32.f16.f16.f32 "
        "{%0,%1,%2,%3}, {%4,%5,%6,%7}, {%8,%9}, {%0,%1,%2,%3};"
        : "+f"(c[0]), "+f"(c[1]), "+f"(c[2]), "+f"(c[3])
        : "r"(a[0]), "r"(a[1]), "r"(a[2]), "r"(a[3]), "r"(b0), "r"(b1));
}

static __device__ __forceinline__ unsigned long long pack_di(float d, int i) {
    return ((unsigned long long)__float_as_uint(d) << 32) | (unsigned)i;
}

// --- k_pre: pack codebook + wnorms + ALL scratch resets ----------------------
__global__ void k_pre(const float* __restrict__ W) {
    const int t    = blockIdx.x * 256 + threadIdx.x;   // 32768 threads
    const int code = t >> 5;
    const int kp   = t & 31;
    float2 v = ((const float2*)(W + (size_t)code * 64))[kp];
    uint32_t h, l;
    split2(v.x, v.y, h, l);
    const int chunk = code >> 7, c = code & 127;
    g_whi[(chunk * 32 + kp) * 128 + c] = h;
    g_wlo[(chunk * 32 + kp) * 128 + c] = l;
    float s = v.x * v.x + v.y * v.y;
    #pragma unroll
    for (int off = 16; off > 0; off >>= 1)
        s += __shfl_xor_sync(~0u, s, off);
    if (kp == 0) g_wnorm[code] = s;
    g_best[t] = 0xFFFFFFFFFFFFFFFFull;
    if (t < 1024) g_counts[t] = 0;
    if (t == 0) { g_loss_sum = 0.f; g_ticket = 0u; }
}

// --- k_main: 512 blocks = 256 row-tiles x 2 code-halves ----------------------
__global__ __launch_bounds__(256, 3)
void k_main(const float* __restrict__ latent, float* __restrict__ out) {
    extern __shared__ __align__(16) char sm[];
    uint32_t* SBHI = (uint32_t*)(sm + SMO_B);
    uint32_t* SBLO = SBHI + 32 * BSTRIDE;
    float*    s_d  = (float*)(sm + SMO_D);
    float*    s_wn = (float*)(sm + SMO_WN);

    const int tid     = threadIdx.x;
    const int blk     = blockIdx.x;
    const int rowtile = blk >> 1;
    const int half    = blk & 1;
    const int w       = tid >> 5;
    const int lane    = tid & 31;
    const int g       = lane >> 2;
    const int tg      = lane & 3;
    const int b       = rowtile >> 3;
    const int jb      = (rowtile & 7) * 128;

    const int row0 = w * 16 + g;
    const int row1 = row0 + 8;

    // this half's code norms (512 floats)
    ((float2*)s_wn)[tid] = ((const float2*)(g_wnorm + half * 512))[tid];

    // ---- A fragments (hi/lo, resident) + fp32 row norms ----
    uint32_t ah[4][4], al[4][4];
    float xn0 = 0.f, xn1 = 0.f;
    {
        const float* LB = latent + (size_t)b * 65536 + jb;
        #pragma unroll
        for (int k = 0; k < 4; k++) {
            const int n0 = 16 * k + 2 * tg;
            float x00 = __ldcs(&LB[(size_t)(n0    ) * 1024 + row0]);
            float x01 = __ldcs(&LB[(size_t)(n0 + 1) * 1024 + row0]);
            float x10 = __ldcs(&LB[(size_t)(n0    ) * 1024 + row1]);
            float x11 = __ldcs(&LB[(size_t)(n0 + 1) * 1024 + row1]);
            float x20 = __ldcs(&LB[(size_t)(n0 + 8) * 1024 + row0]);
            float x21 = __ldcs(&LB[(size_t)(n0 + 9) * 1024 + row0]);
            float x30 = __ldcs(&LB[(size_t)(n0 + 8) * 1024 + row1]);
            float x31 = __ldcs(&LB[(size_t)(n0 + 9) * 1024 + row1]);
            split2(x00, x01, ah[k][0], al[k][0]);
            split2(x10, x11, ah[k][1], al[k][1]);
            split2(x20, x21, ah[k][2], al[k][2]);
            split2(x30, x31, ah[k][3], al[k][3]);
            xn0 += x00*x00 + x01*x01 + x20*x20 + x21*x21;
            xn1 += x10*x10 + x11*x11 + x30*x30 + x31*x31;
        }
        xn0 += __shfl_xor_sync(~0u, xn0, 1);
        xn0 += __shfl_xor_sync(~0u, xn0, 2);
        xn1 += __shfl_xor_sync(~0u, xn1, 1);
        xn1 += __shfl_xor_sync(~0u, xn1, 2);
    }

    float vmin0 = 3.4e38f, vmin1 = 3.4e38f;
    int   imin0 = 0,       imin1 = 0;
    const float2 zero2 = make_float2(0.f, 0.f);

    for (int ch4 = 0; ch4 < 4; ch4++) {
        const int ch = half * 4 + ch4;      // global chunk

        // ---- stage prepacked B chunk (LDG.128 -> STS.128) ----
        {
            const uint4* GH = (const uint4*)(g_whi + ch * 4096);
            const uint4* GL = (const uint4*)(g_wlo + ch * 4096);
            #pragma unroll
            for (int q = 0; q < 4; q++) {
                const int idx = tid + q * 256;
                const int kp = idx >> 5, c4 = idx & 31;
                *(uint4*)&SBHI[kp * BSTRIDE + c4 * 4] = GH[idx];
                *(uint4*)&SBLO[kp * BSTRIDE + c4 * 4] = GL[idx];
            }
        }
        // ---- enc zero-fill for this (rowtile, chunk) slice ----
        {
            float2* eb = (float2*)(out + OFF_ENC) +
                         (size_t)(rowtile * 128) * 512 + half * 256 + ch4 * 64;
            #pragma unroll
            for (int i = 0; i < 32; i++) {
                const int idx = i * 256 + tid;
                const int r = idx >> 6, c2 = idx & 63;
                __stcs(eb + (size_t)r * 512 + c2, zero2);
            }
        }
        __syncthreads();   // staging visible; prev s_d consumed

        #pragma unroll
        for (int hg = 0; hg < 2; hg++) {
            // two quarter passes of 4 tiles (acc 16 regs in flight)
            #pragma unroll
            for (int q = 0; q < 2; q++) {
                float acc[4][4];
                #pragma unroll
                for (int t4 = 0; t4 < 4; t4++) {
                    acc[t4][0] = 0.f; acc[t4][1] = 0.f;
                    acc[t4][2] = 0.f; acc[t4][3] = 0.f;
                }
                #pragma unroll
                for (int k = 0; k < 4; k++) {
                    #pragma unroll
                    for (int t4 = 0; t4 < 4; t4++) {
                        const int nb = (hg * 8 + q * 4 + t4) * 8 + g;
                        const int kp = k * 8 + tg;
                        uint32_t bh0 = SBHI[(kp    ) * BSTRIDE + nb];
                        uint32_t bh1 = SBHI[(kp + 4) * BSTRIDE + nb];
                        uint32_t bl0 = SBLO[(kp    ) * BSTRIDE + nb];
                        uint32_t bl1 = SBLO[(kp + 4) * BSTRIDE + nb];
                        mma16816(acc[t4], ah[k], bh0, bh1);   // hi*hi
                        mma16816(acc[t4], al[k], bh0, bh1);   // lo*hi
                        mma16816(acc[t4], ah[k], bl0, bl1);   // hi*lo
                    }
                }
                #pragma unroll
                for (int t4 = 0; t4 < 4; t4++) {
                    const int cl   = (q * 4 + t4) * 8 + 2 * tg;   // col in half
                    const int lcol = ch4 * 128 + hg * 64 + cl;    // col in 512
                    const int gcol = half * 512 + lcol;
                    const float2 wn = *(const float2*)&s_wn[lcol];
                    float d00 = fmaf(-2.f, acc[t4][0], xn0 + wn.x);
                    float d01 = fmaf(-2.f, acc[t4][1], xn0 + wn.y);
                    float d10 = fmaf(-2.f, acc[t4][2], xn1 + wn.x);
                    float d11 = fmaf(-2.f, acc[t4][3], xn1 + wn.y);
                    *(float2*)&s_d[row0 * DSTRIDE + cl] = make_float2(d00, d01);
                    *(float2*)&s_d[row1 * DSTRIDE + cl] = make_float2(d10, d11);
                    if (d00 < vmin0) { vmin0 = d00; imin0 = gcol; }
                    if (d01 < vmin0) { vmin0 = d01; imin0 = gcol + 1; }
                    if (d10 < vmin1) { vmin1 = d10; imin1 = gcol; }
                    if (d11 < vmin1) { vmin1 = d11; imin1 = gcol + 1; }
                }
            }
            __syncthreads();
            // coalesced stores of this 64-col half-chunk
            {
                float2* db = (float2*)(out + OFF_DIST) +
                             (size_t)(rowtile * 128) * 512 +
                             half * 256 + ch4 * 64 + hg * 32;
                #pragma unroll
                for (int i = 0; i < 16; i++) {
                    const int idx = i * 256 + tid;
                    const int r = idx >> 5, c2 = idx & 31;
                    __stcs(&db[(size_t)r * 512 + c2],
                           *(const float2*)&s_d[r * DSTRIDE + 2 * c2]);
                }
            }
            __syncthreads();
        }
    }

    // ---- argmin across tg lanes, then cross-block u64 atomicMin ----
    #pragma unroll
    for (int off = 1; off <= 2; off <<= 1) {
        float ov0 = __shfl_xor_sync(~0u, vmin0, off);
        int   oi0 = __shfl_xor_sync(~0u, imin0, off);
        if (ov0 < vmin0 || (ov0 == vmin0 && oi0 < imin0)) { vmin0 = ov0; imin0 = oi0; }
        float ov1 = __shfl_xor_sync(~0u, vmin1, off);
        int   oi1 = __shfl_xor_sync(~0u, imin1, off);
        if (ov1 < vmin1 || (ov1 == vmin1 && oi1 < imin1)) { vmin1 = ov1; imin1 = oi1; }
    }
    if (tg == 0) {
        atomicMin(&g_best[rowtile * 128 + row0], pack_di(vmin0, imin0));
        atomicMin(&g_best[rowtile * 128 + row1], pack_di(vmin1, imin1));
    }
}

// --- k_post: one-hot + counts + loss + quantized gather + ticket finalizer ---
__global__ __launch_bounds__(256)
void k_post(const float* __restrict__ W, float* __restrict__ out) {
    __shared__ int   s_idx[64];
    __shared__ float s_wq[64 * 65];
    __shared__ float s_l[8];
    __shared__ int   s_last;

    const int tid  = threadIdx.x;
    const int lane = tid & 31;
    const int t0   = blockIdx.x * 64;

    if (tid < 64) {
        const unsigned long long bv = g_best[t0 + tid];
        const int idx = (int)(unsigned)(bv & 0xFFFFFFFFull);
        float d = __uint_as_float((unsigned)(bv >> 32));
        s_idx[tid] = idx;
        atomicAdd(&g_counts[idx], 1);
        out[OFF_ENC + (size_t)(t0 + tid) * 1024 + idx] = 1.f;
        #pragma unroll
        for (int off = 16; off > 0; off >>= 1)
            d += __shfl_down_sync(~0u, d, off);
        if (lane == 0) s_l[tid >> 5] = d;
    }
    __syncthreads();
    if (tid == 0) atomicAdd(&g_loss_sum, s_l[0] + s_l[1]);

    // quantized gather: stage W[idx] rows (stride-65), coalesced writes
    {
        const int gr = tid >> 2, gq = tid & 3;
        const float4* wp = (const float4*)(W + (size_t)s_idx[gr] * 64) + gq * 4;
        #pragma unroll
        for (int q = 0; q < 4; q++) {
            float4 v = wp[q];
            const int kk = (gq * 4 + q) * 4;
            s_wq[(kk + 0) * 65 + gr] = v.x;
            s_wq[(kk + 1) * 65 + gr] = v.y;
            s_wq[(kk + 2) * 65 + gr] = v.z;
            s_wq[(kk + 3) * 65 + gr] = v.w;
        }
    }
    __syncthreads();
    {
        const int b = t0 >> 10, pos0 = t0 & 1023;
        float* qb = out + OFF_Q + (size_t)b * 65536 + pos0;
        #pragma unroll
        for (int i = 0; i < 16; i++) {
            const int idx = i * 256 + tid;
            const int n = idx >> 6, r = idx & 63;
            __stcs(&qb[(size_t)n * 1024 + r], s_wq[n * 65 + r]);
        }
    }

    // ---- ticket: last block finalizes scalars ----
    __syncthreads();
    if (tid == 0) {
        __threadfence();
        unsigned tkt = atomicAdd(&g_ticket, 1u);
        s_last = (tkt == (unsigned)(gridDim.x - 1));
    }
    __syncthreads();
    if (s_last) {
        __threadfence();
        float part = 0.f;
        #pragma unroll
        for (int i = 0; i < 4; i++) {
            const int k = tid * 4 + i;
            const float p = (float)g_counts[k] / 32768.0f;
            part += -p * logf(p + 1e-10f);
        }
        #pragma unroll
        for (int off = 16; off > 0; off >>= 1)
            part += __shfl_down_sync(~0u, part, off);
        if (lane == 0) s_l[tid >> 5] = part;
        __syncthreads();
        if (tid == 0) {
            float s = 0.f;
            #pragma unroll
            for (int i = 0; i < 8; i++) s += s_l[i];
            out[OFF_PERP] = expf(s);
            out[OFF_LOSS] = 0.25f * g_loss_sum / 2097152.0f;
        }
    }
}

// -----------------------------------------------------------------------------
extern "C" void kernel_launch(void* const* d_in, const int* in_sizes, int n_in,
                              void* d_out, int out_size) {
    const float* latent = (const float*)d_in[0];
    const float* W      = (const float*)d_in[1];
    float* out = (float*)d_out;

    cudaFuncAttributes fa;
    cudaFuncGetAttributes(&fa, k_main);
    if (fa.maxDynamicSharedSizeBytes < SMEM_BYTES)
        cudaFuncSetAttribute(k_main, cudaFuncAttributeMaxDynamicSharedMemorySize,
                             SMEM_BYTES);

    k_pre <<<128, 256>>>(W);
    k_main<<<512, 256, SMEM_BYTES>>>(latent, out);
    k_post<<<512, 256>>>(W, out);
}

// round 15
// speedup vs baseline: 1.6578x; 1.6578x over previous
#include <cuda_runtime.h>
#include <cuda_fp16.h>
#include <cstdint>

#define OFF_Q    0ull
#define OFF_LOSS 2097152ull
#define OFF_PERP 2097153ull
#define OFF_ENC  2097154ull
#define OFF_DIST 35651586ull

#define S64 132   // u64 stride for paired B rows: conflict-free LDS.64 phases

// dynamic smem partition (bytes)
#define SMO_B    0            // u64[16*132] x2 (hi|lo) = 33792 (wq reuse later)
#define SMO_D    33792        // float[128*68] = 34816 (dist staging)
#define SMO_WN   68608        // float[1024]
#define SMO_RMIN 72704        // float[128]
#define SMO_RIDX 73216        // int[128]
#define SMO_LOSS 73728        // float[8]
#define SMEM_BYTES 73760

__device__ int      g_counts[1024];
__device__ float    g_loss_sum;
__device__ float    g_wnorm[1024];
// codebook packed fp16, PAIRED: [chunk(8)][pair(16)][code(128)][2]
// pair p = (kp>>3)*4 + (kp&3); u64 = (frag kp, frag kp+4)
__device__ __align__(16) uint32_t g_wh[32768];
__device__ __align__(16) uint32_t g_wl[32768];

static __device__ __forceinline__ void split2(float x, float y,
                                              uint32_t& hi, uint32_t& lo) {
    __half hx = __float2half_rn(x), hy = __float2half_rn(y);
    float rx = x - __half2float(hx), ry = y - __half2float(hy);
    __half2 h = __halves2half2(hx, hy);
    __half2 l = __floats2half2_rn(rx, ry);
    hi = *(uint32_t*)&h;
    lo = *(uint32_t*)&l;
}

static __device__ __forceinline__ void mma16816(float* c, const uint32_t* a,
                                                uint32_t b0, uint32_t b1) {
    asm volatile(
        "mma.sync.aligned.m16n8k16.row.col.f32.f16.f16.f32 "
        "{%0,%1,%2,%3}, {%4,%5,%6,%7}, {%8,%9}, {%0,%1,%2,%3};"
        : "+f"(c[0]), "+f"(c[1]), "+f"(c[2]), "+f"(c[3])
        : "r"(a[0]), "r"(a[1]), "r"(a[2]), "r"(a[3]), "r"(b0), "r"(b1));
}

// --- k_pre: pack codebook (paired layout) + wnorms + scratch reset -----------
__global__ void k_pre(const float* __restrict__ W) {
    const int t    = blockIdx.x * 256 + threadIdx.x;   // 32768 threads
    const int code = t >> 5;
    const int kp   = t & 31;
    float2 v = ((const float2*)(W + (size_t)code * 64))[kp];
    uint32_t h, l;
    split2(v.x, v.y, h, l);
    const int chunk = code >> 7, c = code & 127;
    const int k   = kp >> 3;
    const int tgp = kp & 7;
    const int p   = k * 4 + (tgp & 3);
    const int hi_half = tgp >> 2;
    const int idx = ((chunk * 16 + p) * 128 + c) * 2 + hi_half;
    g_wh[idx] = h;
    g_wl[idx] = l;
    float s = v.x * v.x + v.y * v.y;
    #pragma unroll
    for (int off = 16; off > 0; off >>= 1)
        s += __shfl_xor_sync(~0u, s, off);
    if (kp == 0) g_wnorm[code] = s;
    if (t < 1024) g_counts[t] = 0;
    if (t == 0)   g_loss_sum  = 0.f;
}

// --- k_main: fused distances(mma) + argmin + enc + quantized + loss ---------
__global__ __launch_bounds__(256, 2)
void k_main(const float* __restrict__ latent, const float* __restrict__ W,
            float* __restrict__ out) {
    extern __shared__ __align__(16) char sm[];
    unsigned long long* SBH = (unsigned long long*)(sm + SMO_B);
    unsigned long long* SBL = SBH + 16 * S64;
    float*    s_d    = (float*)(sm + SMO_D);
    float*    s_wn   = (float*)(sm + SMO_WN);
    float*    s_rmin = (float*)(sm + SMO_RMIN);
    int*      s_ridx = (int*)  (sm + SMO_RIDX);
    float*    s_loss = (float*)(sm + SMO_LOSS);

    const int tid  = threadIdx.x;
    const int blk  = blockIdx.x;
    const int w    = tid >> 5;
    const int lane = tid & 31;
    const int g    = lane >> 2;
    const int tg   = lane & 3;
    const int b    = blk >> 3;
    const int jb   = (blk & 7) * 128;

    const int row0 = w * 16 + g;
    const int row1 = row0 + 8;

    ((float4*)s_wn)[tid] = ((const float4*)g_wnorm)[tid];

    // ---- A fragments (hi/lo, resident) + fp32 row norms ----
    uint32_t ah[4][4], al[4][4];
    float xn0 = 0.f, xn1 = 0.f;
    {
        const float* LB = latent + (size_t)b * 65536 + jb;
        #pragma unroll
        for (int k = 0; k < 4; k++) {
            const int n0 = 16 * k + 2 * tg;
            float x00 = __ldcs(&LB[(size_t)(n0    ) * 1024 + row0]);
            float x01 = __ldcs(&LB[(size_t)(n0 + 1) * 1024 + row0]);
            float x10 = __ldcs(&LB[(size_t)(n0    ) * 1024 + row1]);
            float x11 = __ldcs(&LB[(size_t)(n0 + 1) * 1024 + row1]);
            float x20 = __ldcs(&LB[(size_t)(n0 + 8) * 1024 + row0]);
            float x21 = __ldcs(&LB[(size_t)(n0 + 9) * 1024 + row0]);
            float x30 = __ldcs(&LB[(size_t)(n0 + 8) * 1024 + row1]);
            float x31 = __ldcs(&LB[(size_t)(n0 + 9) * 1024 + row1]);
            split2(x00, x01, ah[k][0], al[k][0]);
            split2(x10, x11, ah[k][1], al[k][1]);
            split2(x20, x21, ah[k][2], al[k][2]);
            split2(x30, x31, ah[k][3], al[k][3]);
            xn0 += x00*x00 + x01*x01 + x20*x20 + x21*x21;
            xn1 += x10*x10 + x11*x11 + x30*x30 + x31*x31;
        }
        xn0 += __shfl_xor_sync(~0u, xn0, 1);
        xn0 += __shfl_xor_sync(~0u, xn0, 2);
        xn1 += __shfl_xor_sync(~0u, xn1, 1);
        xn1 += __shfl_xor_sync(~0u, xn1, 2);
    }

    float vmin0 = 3.4e38f, vmin1 = 3.4e38f;
    int   imin0 = 0,       imin1 = 0;
    const float2 zero2 = make_float2(0.f, 0.f);

    for (int ch = 0; ch < 8; ch++) {
        __syncthreads();   // prev chunk's mma + staging reads done

        // ---- stage prepacked paired B chunk (uint4 LDG -> uint4 STS) ----
        {
            const uint4* GH = (const uint4*)(g_wh + ch * 4096);   // 1024 uint4
            const uint4* GL = (const uint4*)(g_wl + ch * 4096);
            uint4* DH = (uint4*)SBH;
            uint4* DL = (uint4*)SBL;
            #pragma unroll
            for (int q = 0; q < 4; q++) {
                const int idx = tid + q * 256;          // 0..1023
                const int p = idx >> 6, c4 = idx & 63;  // pair row, uint4 col
                DH[p * 66 + c4] = GH[idx];              // 66 uint4 = 132 u64
                DL[p * 66 + c4] = GL[idx];
            }
        }
        __syncthreads();

        // ---- coalesced streaming zero-fill of this chunk's enc slice ----
        {
            float2* eb = (float2*)(out + OFF_ENC) + (size_t)blk * 65536 + ch * 64;
            #pragma unroll
            for (int i = 0; i < 32; i++) {
                const int idx = i * 256 + tid;
                const int r = idx >> 6, c2 = idx & 63;
                __stcs(eb + (size_t)r * 512 + c2, zero2);
            }
        }

        // ---- two col-halves: mma 8 tiles -> stage d in smem -> coalesced STG
        #pragma unroll
        for (int hg = 0; hg < 2; hg++) {
            float acc[8][4];
            #pragma unroll
            for (int tt = 0; tt < 8; tt++) {
                acc[tt][0] = 0.f; acc[tt][1] = 0.f;
                acc[tt][2] = 0.f; acc[tt][3] = 0.f;
            }
            #pragma unroll
            for (int k = 0; k < 4; k++) {
                const int prow = (k * 4 + tg) * S64;
                #pragma unroll
                for (int tt = 0; tt < 8; tt++) {
                    const int nb = (hg * 8 + tt) * 8 + g;
                    unsigned long long bh = SBH[prow + nb];   // LDS.64
                    unsigned long long bl = SBL[prow + nb];   // LDS.64
                    uint32_t bh0 = (uint32_t)bh, bh1 = (uint32_t)(bh >> 32);
                    uint32_t bl0 = (uint32_t)bl, bl1 = (uint32_t)(bl >> 32);
                    mma16816(acc[tt], ah[k], bh0, bh1);   // hi*hi
                    mma16816(acc[tt], al[k], bh0, bh1);   // lo*hi
                    mma16816(acc[tt], ah[k], bl0, bl1);   // hi*lo
                }
            }
            #pragma unroll
            for (int tt = 0; tt < 8; tt++) {
                const int cl  = tt * 8 + 2 * tg;            // col within half
                const int clc = hg * 64 + cl;               // col within chunk
                const int col = ch * 128 + clc;             // global col
                const float2 wn = *(const float2*)&s_wn[col];
                float d00 = fmaf(-2.f, acc[tt][0], xn0 + wn.x);
                float d01 = fmaf(-2.f, acc[tt][1], xn0 + wn.y);
                float d10 = fmaf(-2.f, acc[tt][2], xn1 + wn.x);
                float d11 = fmaf(-2.f, acc[tt][3], xn1 + wn.y);
                *(float2*)&s_d[row0 * 68 + cl] = make_float2(d00, d01);
                *(float2*)&s_d[row1 * 68 + cl] = make_float2(d10, d11);
                if (d00 < vmin0) { vmin0 = d00; imin0 = col; }
                if (d01 < vmin0) { vmin0 = d01; imin0 = col + 1; }
                if (d10 < vmin1) { vmin1 = d10; imin1 = col; }
                if (d11 < vmin1) { vmin1 = d11; imin1 = col + 1; }
            }
            __syncthreads();
            // coalesced float2 stores: warp = one row (256B)
            {
                const int r8 = tid >> 5;
                float2* db = (float2*)(out + OFF_DIST) +
                             ((size_t)blk * 128) * 512 + ch * 64 + hg * 32;
                #pragma unroll
                for (int i = 0; i < 16; i++) {
                    const int r = i * 8 + r8;
                    __stcs(&db[(size_t)r * 512 + lane],
                           *(const float2*)&s_d[r * 68 + lane * 2]);
                }
            }
            __syncthreads();   // s_d reusable
        }
    }

    // ---- argmin across tg lanes (rows are warp-exclusive) ----
    #pragma unroll
    for (int off = 1; off <= 2; off <<= 1) {
        float ov0 = __shfl_xor_sync(~0u, vmin0, off);
        int   oi0 = __shfl_xor_sync(~0u, imin0, off);
        if (ov0 < vmin0 || (ov0 == vmin0 && oi0 < imin0)) { vmin0 = ov0; imin0 = oi0; }
        float ov1 = __shfl_xor_sync(~0u, vmin1, off);
        int   oi1 = __shfl_xor_sync(~0u, imin1, off);
        if (ov1 < vmin1 || (ov1 == vmin1 && oi1 < imin1)) { vmin1 = ov1; imin1 = oi1; }
    }
    if (tg == 0) {
        s_rmin[row0] = vmin0; s_ridx[row0] = imin0;
        s_rmin[row1] = vmin1; s_ridx[row1] = imin1;
    }
    __syncthreads();

    if (tid < 128) {
        const int ii = s_ridx[tid];
        atomicAdd(&g_counts[ii], 1);
        out[OFF_ENC + (size_t)(blk * 128 + tid) * 1024 + ii] = 1.f;
        float v = s_rmin[tid];
        #pragma unroll
        for (int off = 16; off > 0; off >>= 1)
            v += __shfl_down_sync(~0u, v, off);
        if ((tid & 31) == 0) s_loss[tid >> 5] = v;
    }
    __syncthreads();
    if (tid == 0)
        atomicAdd(&g_loss_sum, s_loss[0] + s_loss[1] + s_loss[2] + s_loss[3]);

    // ---- quantized gather: stride-129 smem stage, coalesced writes ----
    {
        float* wq = (float*)SBH;
        const int code = tid >> 1, gh = tid & 1;
        const float4* wp = (const float4*)(W + (size_t)s_ridx[code] * 64) + gh * 8;
        #pragma unroll
        for (int q = 0; q < 8; q++) {
            float4 v = wp[q];
            const int kk = (gh * 8 + q) * 4;
            wq[(kk + 0) * 129 + code] = v.x;
            wq[(kk + 1) * 129 + code] = v.y;
            wq[(kk + 2) * 129 + code] = v.z;
            wq[(kk + 3) * 129 + code] = v.w;
        }
        __syncthreads();
        float* qb = out + OFF_Q + (size_t)b * 65536 + jb;
        #pragma unroll
        for (int i = 0; i < 32; i++) {
            const int idx = i * 256 + tid;
            const int n = idx >> 7, rr = idx & 127;
            __stcs(&qb[(size_t)n * 1024 + rr], wq[n * 129 + rr]);
        }
    }
}

// --- k_final: perplexity + loss ----------------------------------------------
__global__ void k_final(float* __restrict__ out) {
    __shared__ float red[1024];
    const int k = threadIdx.x;
    const float p = (float)g_counts[k] / 32768.0f;
    red[k] = -p * logf(p + 1e-10f);
    __syncthreads();
    for (int s = 512; s > 0; s >>= 1) {
        if (k < s) red[k] += red[k + s];
        __syncthreads();
    }
    if (k == 0) {
        out[OFF_PERP] = expf(red[0]);
        out[OFF_LOSS] = 0.25f * g_loss_sum / 2097152.0f;
    }
}

// -----------------------------------------------------------------------------
extern "C" void kernel_launch(void* const* d_in, const int* in_sizes, int n_in,
                              void* d_out, int out_size) {
    const float* latent = (const float*)d_in[0];
    const float* W      = (const float*)d_in[1];
    float* out = (float*)d_out;

    cudaFuncAttributes fa;
    cudaFuncGetAttributes(&fa, k_main);
    if (fa.maxDynamicSharedSizeBytes < SMEM_BYTES)
        cudaFuncSetAttribute(k_main, cudaFuncAttributeMaxDynamicSharedMemorySize,
                             SMEM_BYTES);

    k_pre  <<<128, 256>>>(W);
    k_main <<<256, 256, SMEM_BYTES>>>(latent, W, out);
    k_final<<<1, 1024>>>(out);
}

// round 16
// speedup vs baseline: 1.6834x; 1.0154x over previous
#include <cuda_runtime.h>
#include <cuda_fp16.h>
#include <cstdint>

#define OFF_Q    0ull
#define OFF_LOSS 2097152ull
#define OFF_PERP 2097153ull
#define OFF_ENC  2097154ull
#define OFF_DIST 35651586ull

#define S64 132   // u64 stride for paired B rows: conflict-free LDS.64 phases

// dynamic smem partition (bytes)
#define SMO_B    0            // u64[16*132] x2 (hi|lo) = 33792 (wq reuse later)
#define SMO_D    33792        // float[128*132] = 67584 (full-width dist staging)
#define SMO_WN   101376       // float[1024]
#define SMO_RMIN 105472       // float[128]
#define SMO_RIDX 105984       // int[128]
#define SMO_LOSS 106496       // float[8]
#define SMEM_BYTES 106528

__device__ int      g_counts[1024];
__device__ float    g_loss_sum;
__device__ float    g_wnorm[1024];
// codebook packed fp16, PAIRED: [chunk(8)][pair(16)][code(128)][2]
// pair p = (kp>>3)*4 + (kp&3); u64 = (frag kp, frag kp+4)
__device__ __align__(16) uint32_t g_wh[32768];
__device__ __align__(16) uint32_t g_wl[32768];

static __device__ __forceinline__ void split2(float x, float y,
                                              uint32_t& hi, uint32_t& lo) {
    __half hx = __float2half_rn(x), hy = __float2half_rn(y);
    float rx = x - __half2float(hx), ry = y - __half2float(hy);
    __half2 h = __halves2half2(hx, hy);
    __half2 l = __floats2half2_rn(rx, ry);
    hi = *(uint32_t*)&h;
    lo = *(uint32_t*)&l;
}

static __device__ __forceinline__ void mma16816(float* c, const uint32_t* a,
                                                uint32_t b0, uint32_t b1) {
    asm volatile(
        "mma.sync.aligned.m16n8k16.row.col.f32.f16.f16.f32 "
        "{%0,%1,%2,%3}, {%4,%5,%6,%7}, {%8,%9}, {%0,%1,%2,%3};"
        : "+f"(c[0]), "+f"(c[1]), "+f"(c[2]), "+f"(c[3])
        : "r"(a[0]), "r"(a[1]), "r"(a[2]), "r"(a[3]), "r"(b0), "r"(b1));
}

// --- k_pre: pack codebook (paired layout) + wnorms + scratch reset -----------
__global__ void k_pre(const float* __restrict__ W) {
    const int t    = blockIdx.x * 256 + threadIdx.x;   // 32768 threads
    const int code = t >> 5;
    const int kp   = t & 31;
    float2 v = ((const float2*)(W + (size_t)code * 64))[kp];
    uint32_t h, l;
    split2(v.x, v.y, h, l);
    const int chunk = code >> 7, c = code & 127;
    const int k   = kp >> 3;
    const int tgp = kp & 7;
    const int p   = k * 4 + (tgp & 3);
    const int hi_half = tgp >> 2;
    const int idx = ((chunk * 16 + p) * 128 + c) * 2 + hi_half;
    g_wh[idx] = h;
    g_wl[idx] = l;
    float s = v.x * v.x + v.y * v.y;
    #pragma unroll
    for (int off = 16; off > 0; off >>= 1)
        s += __shfl_xor_sync(~0u, s, off);
    if (kp == 0) g_wnorm[code] = s;
    if (t < 1024) g_counts[t] = 0;
    if (t == 0)   g_loss_sum  = 0.f;
}

// --- k_main: fused distances(mma) + argmin + enc + quantized + loss ---------
__global__ __launch_bounds__(256, 2)
void k_main(const float* __restrict__ latent, const float* __restrict__ W,
            float* __restrict__ out) {
    extern __shared__ __align__(16) char sm[];
    unsigned long long* SBH = (unsigned long long*)(sm + SMO_B);
    unsigned long long* SBL = SBH + 16 * S64;
    float*    s_d    = (float*)(sm + SMO_D);
    float*    s_wn   = (float*)(sm + SMO_WN);
    float*    s_rmin = (float*)(sm + SMO_RMIN);
    int*      s_ridx = (int*)  (sm + SMO_RIDX);
    float*    s_loss = (float*)(sm + SMO_LOSS);

    const int tid  = threadIdx.x;
    const int blk  = blockIdx.x;
    const int w    = tid >> 5;
    const int lane = tid & 31;
    const int g    = lane >> 2;
    const int tg   = lane & 3;
    const int b    = blk >> 3;
    const int jb   = (blk & 7) * 128;

    const int row0 = w * 16 + g;
    const int row1 = row0 + 8;

    ((float4*)s_wn)[tid] = ((const float4*)g_wnorm)[tid];

    // ---- A fragments (hi/lo, resident) + fp32 row norms ----
    uint32_t ah[4][4], al[4][4];
    float xn0 = 0.f, xn1 = 0.f;
    {
        const float* LB = latent + (size_t)b * 65536 + jb;
        #pragma unroll
        for (int k = 0; k < 4; k++) {
            const int n0 = 16 * k + 2 * tg;
            float x00 = __ldcs(&LB[(size_t)(n0    ) * 1024 + row0]);
            float x01 = __ldcs(&LB[(size_t)(n0 + 1) * 1024 + row0]);
            float x10 = __ldcs(&LB[(size_t)(n0    ) * 1024 + row1]);
            float x11 = __ldcs(&LB[(size_t)(n0 + 1) * 1024 + row1]);
            float x20 = __ldcs(&LB[(size_t)(n0 + 8) * 1024 + row0]);
            float x21 = __ldcs(&LB[(size_t)(n0 + 9) * 1024 + row0]);
            float x30 = __ldcs(&LB[(size_t)(n0 + 8) * 1024 + row1]);
            float x31 = __ldcs(&LB[(size_t)(n0 + 9) * 1024 + row1]);
            split2(x00, x01, ah[k][0], al[k][0]);
            split2(x10, x11, ah[k][1], al[k][1]);
            split2(x20, x21, ah[k][2], al[k][2]);
            split2(x30, x31, ah[k][3], al[k][3]);
            xn0 += x00*x00 + x01*x01 + x20*x20 + x21*x21;
            xn1 += x10*x10 + x11*x11 + x30*x30 + x31*x31;
        }
        xn0 += __shfl_xor_sync(~0u, xn0, 1);
        xn0 += __shfl_xor_sync(~0u, xn0, 2);
        xn1 += __shfl_xor_sync(~0u, xn1, 1);
        xn1 += __shfl_xor_sync(~0u, xn1, 2);
    }

    float vmin0 = 3.4e38f, vmin1 = 3.4e38f;
    int   imin0 = 0,       imin1 = 0;
    const float2 zero2 = make_float2(0.f, 0.f);

    for (int ch = 0; ch < 8; ch++) {
        // ---- stage prepacked paired B chunk (uint4 LDG -> uint4 STS) ----
        // safe concurrently with other warps' prev-chunk store phase:
        // stage touches SBH/SBL, store touches s_d/global only.
        {
            const uint4* GH = (const uint4*)(g_wh + ch * 4096);   // 1024 uint4
            const uint4* GL = (const uint4*)(g_wl + ch * 4096);
            uint4* DH = (uint4*)SBH;
            uint4* DL = (uint4*)SBL;
            #pragma unroll
            for (int q = 0; q < 4; q++) {
                const int idx = tid + q * 256;          // 0..1023
                const int p = idx >> 6, c4 = idx & 63;  // pair row, uint4 col
                DH[p * 66 + c4] = GH[idx];              // 66 uint4 = 132 u64
                DL[p * 66 + c4] = GL[idx];
            }
        }
        // ---- coalesced streaming zero-fill of this chunk's enc slice ----
        {
            float2* eb = (float2*)(out + OFF_ENC) + (size_t)blk * 65536 + ch * 64;
            #pragma unroll
            for (int i = 0; i < 32; i++) {
                const int idx = i * 256 + tid;
                const int r = idx >> 6, c2 = idx & 63;
                __stcs(eb + (size_t)r * 512 + c2, zero2);
            }
        }
        __syncthreads();   // staging visible; prev store phase done (s_d free)

        // ---- 4 passes of 4 tiles; 3 independent accs per tile ----
        #pragma unroll
        for (int p = 0; p < 4; p++) {
            float ahh[4][4], alh[4][4], ahl[4][4];
            #pragma unroll
            for (int t4 = 0; t4 < 4; t4++)
                #pragma unroll
                for (int e = 0; e < 4; e++) {
                    ahh[t4][e] = 0.f; alh[t4][e] = 0.f; ahl[t4][e] = 0.f;
                }
            #pragma unroll
            for (int k = 0; k < 4; k++) {
                const int prow = (k * 4 + tg) * S64;
                #pragma unroll
                for (int t4 = 0; t4 < 4; t4++) {
                    const int nb = (p * 4 + t4) * 8 + g;
                    unsigned long long bh = SBH[prow + nb];   // LDS.64
                    unsigned long long bl = SBL[prow + nb];   // LDS.64
                    uint32_t bh0 = (uint32_t)bh, bh1 = (uint32_t)(bh >> 32);
                    uint32_t bl0 = (uint32_t)bl, bl1 = (uint32_t)(bl >> 32);
                    mma16816(ahh[t4], ah[k], bh0, bh1);   // hi*hi
                    mma16816(alh[t4], al[k], bh0, bh1);   // lo*hi
                    mma16816(ahl[t4], ah[k], bl0, bl1);   // hi*lo
                }
            }
            #pragma unroll
            for (int t4 = 0; t4 < 4; t4++) {
                const int cl  = (p * 4 + t4) * 8 + 2 * tg;  // col within chunk
                const int col = ch * 128 + cl;
                const float2 wn = *(const float2*)&s_wn[col];
                float s0 = ahh[t4][0] + alh[t4][0] + ahl[t4][0];
                float s1 = ahh[t4][1] + alh[t4][1] + ahl[t4][1];
                float s2 = ahh[t4][2] + alh[t4][2] + ahl[t4][2];
                float s3 = ahh[t4][3] + alh[t4][3] + ahl[t4][3];
                float d00 = fmaf(-2.f, s0, xn0 + wn.x);
                float d01 = fmaf(-2.f, s1, xn0 + wn.y);
                float d10 = fmaf(-2.f, s2, xn1 + wn.x);
                float d11 = fmaf(-2.f, s3, xn1 + wn.y);
                *(float2*)&s_d[row0 * 132 + cl] = make_float2(d00, d01);
                *(float2*)&s_d[row1 * 132 + cl] = make_float2(d10, d11);
                if (d00 < vmin0) { vmin0 = d00; imin0 = col; }
                if (d01 < vmin0) { vmin0 = d01; imin0 = col + 1; }
                if (d10 < vmin1) { vmin1 = d10; imin1 = col; }
                if (d11 < vmin1) { vmin1 = d11; imin1 = col + 1; }
            }
        }
        __syncthreads();   // s_d complete; SBH/SBL consumed

        // ---- coalesced float2 stores of the full chunk ----
        {
            float2* db = (float2*)(out + OFF_DIST) +
                         ((size_t)blk * 128) * 512 + ch * 64;
            #pragma unroll
            for (int i = 0; i < 32; i++) {
                const int idx = i * 256 + tid;
                const int r = idx >> 6, c2 = idx & 63;
                __stcs(&db[(size_t)r * 512 + c2],
                       *(const float2*)&s_d[r * 132 + 2 * c2]);
            }
        }
        // no sync here: next iteration's top sync covers s_d reuse
    }

    // ---- argmin across tg lanes (rows are warp-exclusive) ----
    #pragma unroll
    for (int off = 1; off <= 2; off <<= 1) {
        float ov0 = __shfl_xor_sync(~0u, vmin0, off);
        int   oi0 = __shfl_xor_sync(~0u, imin0, off);
        if (ov0 < vmin0 || (ov0 == vmin0 && oi0 < imin0)) { vmin0 = ov0; imin0 = oi0; }
        float ov1 = __shfl_xor_sync(~0u, vmin1, off);
        int   oi1 = __shfl_xor_sync(~0u, imin1, off);
        if (ov1 < vmin1 || (ov1 == vmin1 && oi1 < imin1)) { vmin1 = ov1; imin1 = oi1; }
    }
    __syncthreads();   // all store phases done before wq reuses SBH
    if (tg == 0) {
        s_rmin[row0] = vmin0; s_ridx[row0] = imin0;
        s_rmin[row1] = vmin1; s_ridx[row1] = imin1;
    }
    __syncthreads();

    if (tid < 128) {
        const int ii = s_ridx[tid];
        atomicAdd(&g_counts[ii], 1);
        out[OFF_ENC + (size_t)(blk * 128 + tid) * 1024 + ii] = 1.f;
        float v = s_rmin[tid];
        #pragma unroll
        for (int off = 16; off > 0; off >>= 1)
            v += __shfl_down_sync(~0u, v, off);
        if ((tid & 31) == 0) s_loss[tid >> 5] = v;
    }
    __syncthreads();
    if (tid == 0)
        atomicAdd(&g_loss_sum, s_loss[0] + s_loss[1] + s_loss[2] + s_loss[3]);

    // ---- quantized gather: stride-129 smem stage, coalesced writes ----
    {
        float* wq = (float*)SBH;
        const int code = tid >> 1, gh = tid & 1;
        const float4* wp = (const float4*)(W + (size_t)s_ridx[code] * 64) + gh * 8;
        #pragma unroll
        for (int q = 0; q < 8; q++) {
            float4 v = wp[q];
            const int kk = (gh * 8 + q) * 4;
            wq[(kk + 0) * 129 + code] = v.x;
            wq[(kk + 1) * 129 + code] = v.y;
            wq[(kk + 2) * 129 + code] = v.z;
            wq[(kk + 3) * 129 + code] = v.w;
        }
        __syncthreads();
        float* qb = out + OFF_Q + (size_t)b * 65536 + jb;
        #pragma unroll
        for (int i = 0; i < 32; i++) {
            const int idx = i * 256 + tid;
            const int n = idx >> 7, rr = idx & 127;
            __stcs(&qb[(size_t)n * 1024 + rr], wq[n * 129 + rr]);
        }
    }
}

// --- k_final: perplexity + loss ----------------------------------------------
__global__ void k_final(float* __restrict__ out) {
    __shared__ float red[1024];
    const int k = threadIdx.x;
    const float p = (float)g_counts[k] / 32768.0f;
    red[k] = -p * logf(p + 1e-10f);
    __syncthreads();
    for (int s = 512; s > 0; s >>= 1) {
        if (k < s) red[k] += red[k + s];
        __syncthreads();
    }
    if (k == 0) {
        out[OFF_PERP] = expf(red[0]);
        out[OFF_LOSS] = 0.25f * g_loss_sum / 2097152.0f;
    }
}

// -----------------------------------------------------------------------------
extern "C" void kernel_launch(void* const* d_in, const int* in_sizes, int n_in,
                              void* d_out, int out_size) {
    const float* latent = (const float*)d_in[0];
    const float* W      = (const float*)d_in[1];
    float* out = (float*)d_out;

    cudaFuncAttributes fa;
    cudaFuncGetAttributes(&fa, k_main);
    if (fa.maxDynamicSharedSizeBytes < SMEM_BYTES)
        cudaFuncSetAttribute(k_main, cudaFuncAttributeMaxDynamicSharedMemorySize,
                             SMEM_BYTES);

    k_pre  <<<128, 256>>>(W);
    k_main <<<256, 256, SMEM_BYTES>>>(latent, W, out);
    k_final<<<1, 1024>>>(out);
}

// round 17
// speedup vs baseline: 1.6846x; 1.0007x over previous
#include <cuda_runtime.h>
#include <cuda_fp16.h>
#include <cstdint>

#define OFF_Q    0ull
#define OFF_LOSS 2097152ull
#define OFF_PERP 2097153ull
#define OFF_ENC  2097154ull
#define OFF_DIST 35651586ull

#define S64 132   // u64 stride for paired B rows: conflict-free LDS.64 phases

// dynamic smem partition (bytes)
#define SMO_B    0            // u64[16*132] x2 (hi|lo) = 33792 (wq reuse later)
#define SMO_D    33792        // float[128*132] = 67584 (full-width dist staging)
#define SMO_WN   101376       // float[1024]
#define SMO_RMIN 105472       // float[128]
#define SMO_RIDX 105984       // int[128]
#define SMO_LOSS 106496       // float[8]
#define SMO_LAST 106528       // int flag
#define SMEM_BYTES 106560

__device__ int      g_counts[1024];
__device__ float    g_loss_sum;
__device__ float    g_wnorm[1024];
__device__ unsigned g_ticket;
// codebook packed fp16, PAIRED: [chunk(8)][pair(16)][code(128)][2]
// pair p = (kp>>3)*4 + (kp&3); u64 = (frag kp, frag kp+4)
__device__ __align__(16) uint32_t g_wh[32768];
__device__ __align__(16) uint32_t g_wl[32768];

static __device__ __forceinline__ void split2(float x, float y,
                                              uint32_t& hi, uint32_t& lo) {
    __half hx = __float2half_rn(x), hy = __float2half_rn(y);
    float rx = x - __half2float(hx), ry = y - __half2float(hy);
    __half2 h = __halves2half2(hx, hy);
    __half2 l = __floats2half2_rn(rx, ry);
    hi = *(uint32_t*)&h;
    lo = *(uint32_t*)&l;
}

static __device__ __forceinline__ void mma16816(float* c, const uint32_t* a,
                                                uint32_t b0, uint32_t b1) {
    asm volatile(
        "mma.sync.aligned.m16n8k16.row.col.f32.f16.f16.f32 "
        "{%0,%1,%2,%3}, {%4,%5,%6,%7}, {%8,%9}, {%0,%1,%2,%3};"
        : "+f"(c[0]), "+f"(c[1]), "+f"(c[2]), "+f"(c[3])
        : "r"(a[0]), "r"(a[1]), "r"(a[2]), "r"(a[3]), "r"(b0), "r"(b1));
}

// --- k_pre: pack codebook (paired layout) + wnorms + scratch reset -----------
__global__ void k_pre(const float* __restrict__ W) {
    const int t    = blockIdx.x * 256 + threadIdx.x;   // 32768 threads
    const int code = t >> 5;
    const int kp   = t & 31;
    float2 v = ((const float2*)(W + (size_t)code * 64))[kp];
    uint32_t h, l;
    split2(v.x, v.y, h, l);
    const int chunk = code >> 7, c = code & 127;
    const int k   = kp >> 3;
    const int tgp = kp & 7;
    const int p   = k * 4 + (tgp & 3);
    const int hi_half = tgp >> 2;
    const int idx = ((chunk * 16 + p) * 128 + c) * 2 + hi_half;
    g_wh[idx] = h;
    g_wl[idx] = l;
    float s = v.x * v.x + v.y * v.y;
    #pragma unroll
    for (int off = 16; off > 0; off >>= 1)
        s += __shfl_xor_sync(~0u, s, off);
    if (kp == 0) g_wnorm[code] = s;
    if (t < 1024) g_counts[t] = 0;
    if (t == 0) { g_loss_sum = 0.f; g_ticket = 0u; }
}

// --- k_main: distances(mma) + argmin + enc + quantized + loss + finalize ----
__global__ __launch_bounds__(256, 2)
void k_main(const float* __restrict__ latent, const float* __restrict__ W,
            float* __restrict__ out) {
    extern __shared__ __align__(16) char sm[];
    unsigned long long* SBH = (unsigned long long*)(sm + SMO_B);
    unsigned long long* SBL = SBH + 16 * S64;
    float*    s_d    = (float*)(sm + SMO_D);
    float*    s_wn   = (float*)(sm + SMO_WN);
    float*    s_rmin = (float*)(sm + SMO_RMIN);
    int*      s_ridx = (int*)  (sm + SMO_RIDX);
    float*    s_loss = (float*)(sm + SMO_LOSS);
    int*      s_last = (int*)  (sm + SMO_LAST);

    const int tid  = threadIdx.x;
    const int blk  = blockIdx.x;
    const int w    = tid >> 5;
    const int lane = tid & 31;
    const int g    = lane >> 2;
    const int tg   = lane & 3;
    const int b    = blk >> 3;
    const int jb   = (blk & 7) * 128;

    const int row0 = w * 16 + g;
    const int row1 = row0 + 8;

    ((float4*)s_wn)[tid] = ((const float4*)g_wnorm)[tid];

    // ---- A fragments (hi/lo, resident) + fp32 row norms ----
    uint32_t ah[4][4], al[4][4];
    float xn0 = 0.f, xn1 = 0.f;
    {
        const float* LB = latent + (size_t)b * 65536 + jb;
        #pragma unroll
        for (int k = 0; k < 4; k++) {
            const int n0 = 16 * k + 2 * tg;
            float x00 = __ldcs(&LB[(size_t)(n0    ) * 1024 + row0]);
            float x01 = __ldcs(&LB[(size_t)(n0 + 1) * 1024 + row0]);
            float x10 = __ldcs(&LB[(size_t)(n0    ) * 1024 + row1]);
            float x11 = __ldcs(&LB[(size_t)(n0 + 1) * 1024 + row1]);
            float x20 = __ldcs(&LB[(size_t)(n0 + 8) * 1024 + row0]);
            float x21 = __ldcs(&LB[(size_t)(n0 + 9) * 1024 + row0]);
            float x30 = __ldcs(&LB[(size_t)(n0 + 8) * 1024 + row1]);
            float x31 = __ldcs(&LB[(size_t)(n0 + 9) * 1024 + row1]);
            split2(x00, x01, ah[k][0], al[k][0]);
            split2(x10, x11, ah[k][1], al[k][1]);
            split2(x20, x21, ah[k][2], al[k][2]);
            split2(x30, x31, ah[k][3], al[k][3]);
            xn0 += x00*x00 + x01*x01 + x20*x20 + x21*x21;
            xn1 += x10*x10 + x11*x11 + x30*x30 + x31*x31;
        }
        xn0 += __shfl_xor_sync(~0u, xn0, 1);
        xn0 += __shfl_xor_sync(~0u, xn0, 2);
        xn1 += __shfl_xor_sync(~0u, xn1, 1);
        xn1 += __shfl_xor_sync(~0u, xn1, 2);
    }

    float vmin0 = 3.4e38f, vmin1 = 3.4e38f;
    int   imin0 = 0,       imin1 = 0;
    const float2 zero2 = make_float2(0.f, 0.f);

    for (int ch = 0; ch < 8; ch++) {
        // ---- stage prepacked paired B chunk (uint4 LDG -> uint4 STS) ----
        {
            const uint4* GH = (const uint4*)(g_wh + ch * 4096);   // 1024 uint4
            const uint4* GL = (const uint4*)(g_wl + ch * 4096);
            uint4* DH = (uint4*)SBH;
            uint4* DL = (uint4*)SBL;
            #pragma unroll
            for (int q = 0; q < 4; q++) {
                const int idx = tid + q * 256;          // 0..1023
                const int p = idx >> 6, c4 = idx & 63;  // pair row, uint4 col
                DH[p * 66 + c4] = GH[idx];              // 66 uint4 = 132 u64
                DL[p * 66 + c4] = GL[idx];
            }
        }
        // ---- coalesced streaming zero-fill of this chunk's enc slice ----
        {
            float2* eb = (float2*)(out + OFF_ENC) + (size_t)blk * 65536 + ch * 64;
            #pragma unroll
            for (int i = 0; i < 32; i++) {
                const int idx = i * 256 + tid;
                const int r = idx >> 6, c2 = idx & 63;
                __stcs(eb + (size_t)r * 512 + c2, zero2);
            }
        }
        __syncthreads();   // staging visible; prev store phase done (s_d free)

        // ---- 4 passes of 4 tiles; 3 independent accs per tile ----
        #pragma unroll
        for (int p = 0; p < 4; p++) {
            float ahh[4][4], alh[4][4], ahl[4][4];
            #pragma unroll
            for (int t4 = 0; t4 < 4; t4++)
                #pragma unroll
                for (int e = 0; e < 4; e++) {
                    ahh[t4][e] = 0.f; alh[t4][e] = 0.f; ahl[t4][e] = 0.f;
                }
            #pragma unroll
            for (int k = 0; k < 4; k++) {
                const int prow = (k * 4 + tg) * S64;
                #pragma unroll
                for (int t4 = 0; t4 < 4; t4++) {
                    const int nb = (p * 4 + t4) * 8 + g;
                    unsigned long long bh = SBH[prow + nb];   // LDS.64
                    unsigned long long bl = SBL[prow + nb];   // LDS.64
                    uint32_t bh0 = (uint32_t)bh, bh1 = (uint32_t)(bh >> 32);
                    uint32_t bl0 = (uint32_t)bl, bl1 = (uint32_t)(bl >> 32);
                    mma16816(ahh[t4], ah[k], bh0, bh1);   // hi*hi
                    mma16816(alh[t4], al[k], bh0, bh1);   // lo*hi
                    mma16816(ahl[t4], ah[k], bl0, bl1);   // hi*lo
                }
            }
            #pragma unroll
            for (int t4 = 0; t4 < 4; t4++) {
                const int cl  = (p * 4 + t4) * 8 + 2 * tg;  // col within chunk
                const int col = ch * 128 + cl;
                const float2 wn = *(const float2*)&s_wn[col];
                float s0 = ahh[t4][0] + alh[t4][0] + ahl[t4][0];
                float s1 = ahh[t4][1] + alh[t4][1] + ahl[t4][1];
                float s2 = ahh[t4][2] + alh[t4][2] + ahl[t4][2];
                float s3 = ahh[t4][3] + alh[t4][3] + ahl[t4][3];
                float d00 = fmaf(-2.f, s0, xn0 + wn.x);
                float d01 = fmaf(-2.f, s1, xn0 + wn.y);
                float d10 = fmaf(-2.f, s2, xn1 + wn.x);
                float d11 = fmaf(-2.f, s3, xn1 + wn.y);
                *(float2*)&s_d[row0 * 132 + cl] = make_float2(d00, d01);
                *(float2*)&s_d[row1 * 132 + cl] = make_float2(d10, d11);
                if (d00 < vmin0) { vmin0 = d00; imin0 = col; }
                if (d01 < vmin0) { vmin0 = d01; imin0 = col + 1; }
                if (d10 < vmin1) { vmin1 = d10; imin1 = col; }
                if (d11 < vmin1) { vmin1 = d11; imin1 = col + 1; }
            }
        }
        __syncthreads();   // s_d complete; SBH/SBL consumed

        // ---- coalesced float2 stores of the full chunk ----
        {
            float2* db = (float2*)(out + OFF_DIST) +
                         ((size_t)blk * 128) * 512 + ch * 64;
            #pragma unroll
            for (int i = 0; i < 32; i++) {
                const int idx = i * 256 + tid;
                const int r = idx >> 6, c2 = idx & 63;
                __stcs(&db[(size_t)r * 512 + c2],
                       *(const float2*)&s_d[r * 132 + 2 * c2]);
            }
        }
        // no sync here: next iteration's top sync covers s_d reuse
    }

    // ---- argmin across tg lanes (rows are warp-exclusive) ----
    #pragma unroll
    for (int off = 1; off <= 2; off <<= 1) {
        float ov0 = __shfl_xor_sync(~0u, vmin0, off);
        int   oi0 = __shfl_xor_sync(~0u, imin0, off);
        if (ov0 < vmin0 || (ov0 == vmin0 && oi0 < imin0)) { vmin0 = ov0; imin0 = oi0; }
        float ov1 = __shfl_xor_sync(~0u, vmin1, off);
        int   oi1 = __shfl_xor_sync(~0u, imin1, off);
        if (ov1 < vmin1 || (ov1 == vmin1 && oi1 < imin1)) { vmin1 = ov1; imin1 = oi1; }
    }
    __syncthreads();   // all store phases done before wq reuses SBH
    if (tg == 0) {
        s_rmin[row0] = vmin0; s_ridx[row0] = imin0;
        s_rmin[row1] = vmin1; s_ridx[row1] = imin1;
    }
    __syncthreads();

    if (tid < 128) {
        const int ii = s_ridx[tid];
        atomicAdd(&g_counts[ii], 1);
        out[OFF_ENC + (size_t)(blk * 128 + tid) * 1024 + ii] = 1.f;
        float v = s_rmin[tid];
        #pragma unroll
        for (int off = 16; off > 0; off >>= 1)
            v += __shfl_down_sync(~0u, v, off);
        if ((tid & 31) == 0) s_loss[tid >> 5] = v;
    }
    __syncthreads();
    if (tid == 0)
        atomicAdd(&g_loss_sum, s_loss[0] + s_loss[1] + s_loss[2] + s_loss[3]);

    // ---- quantized gather: stride-129 smem stage, coalesced writes ----
    {
        float* wq = (float*)SBH;
        const int code = tid >> 1, gh = tid & 1;
        const float4* wp = (const float4*)(W + (size_t)s_ridx[code] * 64) + gh * 8;
        #pragma unroll
        for (int q = 0; q < 8; q++) {
            float4 v = wp[q];
            const int kk = (gh * 8 + q) * 4;
            wq[(kk + 0) * 129 + code] = v.x;
            wq[(kk + 1) * 129 + code] = v.y;
            wq[(kk + 2) * 129 + code] = v.z;
            wq[(kk + 3) * 129 + code] = v.w;
        }
        __syncthreads();
        float* qb = out + OFF_Q + (size_t)b * 65536 + jb;
        #pragma unroll
        for (int i = 0; i < 32; i++) {
            const int idx = i * 256 + tid;
            const int n = idx >> 7, rr = idx & 127;
            __stcs(&qb[(size_t)n * 1024 + rr], wq[n * 129 + rr]);
        }
    }

    // ---- ticket: last block finalizes perplexity + loss ----
    __syncthreads();
    if (tid == 0) {
        __threadfence();                       // order counts/loss atomics
        unsigned t = atomicAdd(&g_ticket, 1u);
        *s_last = (t == (unsigned)(gridDim.x - 1));
    }
    __syncthreads();
    if (*s_last) {
        __threadfence();
        float part = 0.f;
        #pragma unroll
        for (int i = 0; i < 4; i++) {
            const int k = tid * 4 + i;
            const float p = (float)g_counts[k] / 32768.0f;
            part += -p * logf(p + 1e-10f);
        }
        #pragma unroll
        for (int off = 16; off > 0; off >>= 1)
            part += __shfl_down_sync(~0u, part, off);
        if (lane == 0) s_loss[w] = part;
        __syncthreads();
        if (tid == 0) {
            float s = 0.f;
            #pragma unroll
            for (int i = 0; i < 8; i++) s += s_loss[i];
            out[OFF_PERP] = expf(s);
            out[OFF_LOSS] = 0.25f * g_loss_sum / 2097152.0f;
        }
    }
}

// -----------------------------------------------------------------------------
extern "C" void kernel_launch(void* const* d_in, const int* in_sizes, int n_in,
                              void* d_out, int out_size) {
    const float* latent = (const float*)d_in[0];
    const float* W      = (const float*)d_in[1];
    float* out = (float*)d_out;

    cudaFuncAttributes fa;
    cudaFuncGetAttributes(&fa, k_main);
    if (fa.maxDynamicSharedSizeBytes < SMEM_BYTES)
        cudaFuncSetAttribute(k_main, cudaFuncAttributeMaxDynamicSharedMemorySize,
                             SMEM_BYTES);

    k_pre  <<<128, 256>>>(W);
    k_main <<<256, 256, SMEM_BYTES>>>(latent, W, out);
}